// round 17
// baseline (speedup 1.0000x reference)
#include <cuda_runtime.h>
#include <cstdint>

#define TSTEPS 512
#define ISZ    8
#define HID    32
#define BC     64
#define NTH    256

typedef unsigned long long u64;

// ---------------- smem layout (bytes) ----------------
#define OFF_AF    0
#define AF_BYTES  (8*13*2*32*16)          // 106496: [w][kb][term][lane] float4
#define OFF_B1X   (OFF_AF + AF_BYTES)     // float2 [2][40][68]  (h1 rows 0-31, x rows 32-39)
#define B1X_BYTES (2*40*68*8)             // 43520
#define OFF_B2    (OFF_B1X + B1X_BYTES)   // float2 [2][32][68]  (h2)
#define B2_BYTES  (2*32*68*8)             // 34816
#define OFF_STG   (OFF_B2 + B2_BYTES)     // float [128][68]
#define STG_BYTES (128*68*4)              // 34816
#define OFF_MISC  (OFF_STG + STG_BYTES)
#define SMEM_TOTAL (OFF_MISC + 4096)      // 223744 total

// ---------------- math helpers (proven R2-R16) ----------------
__device__ __forceinline__ u64 dup2(float x){u64 r;asm("mov.b64 %0,{%1,%1};":"=l"(r):"f"(x));return r;}
__device__ __forceinline__ u64 pk2(float a,float b){u64 r;asm("mov.b64 %0,{%1,%2};":"=l"(r):"f"(a),"f"(b));return r;}
__device__ __forceinline__ void up2(u64 v,float&a,float&b){asm("mov.b64 {%0,%1},%2;":"=f"(a),"=f"(b):"l"(v));}
__device__ __forceinline__ u64 fadd2(u64 a,u64 b){u64 d;asm("add.rn.f32x2 %0,%1,%2;":"=l"(d):"l"(a),"l"(b));return d;}
__device__ __forceinline__ float ex2a(float x){float y;asm("ex2.approx.f32 %0,%1;":"=f"(y):"f"(x));return y;}
__device__ __forceinline__ float rcpa(float x){float y;asm("rcp.approx.f32 %0,%1;":"=f"(y):"f"(x));return y;}
__device__ __forceinline__ float sigf(float x){return rcpa(1.0f+ex2a(-1.4426950408889634f*x));}
__device__ __forceinline__ float tanhfx(float x){return 1.0f-2.0f*rcpa(1.0f+ex2a(2.8853900817779268f*x));}
__device__ __forceinline__ u64 lstm_act(u64 gi,u64 gf,u64 gg,u64 go,u64&c){
    float a,b;
    up2(gi,a,b); float i0=sigf(a),i1=sigf(b);
    up2(gf,a,b); float f0=sigf(a),f1=sigf(b);
    up2(gg,a,b); float g0=tanhfx(a),g1=tanhfx(b);
    up2(go,a,b); float o0=sigf(a),o1=sigf(b);
    float c0,c1; up2(c,c0,c1);
    c0=f0*c0+i0*g0; c1=f1*c1+i1*g1; c=pk2(c0,c1);
    return pk2(o0*tanhfx(c0),o1*tanhfx(c1));
}
__device__ __forceinline__ void tf32s(float v,float&hi,float&lo){
    uint32_t b; asm("cvt.rna.tf32.f32 %0,%1;":"=r"(b):"f"(v)); hi=__uint_as_float(b);
    float r=v-hi; asm("cvt.rna.tf32.f32 %0,%1;":"=r"(b):"f"(r)); lo=__uint_as_float(b);
}

// ---------------- warp-level tf32 MMA (arch-generic HMMA path) ----------------
__device__ __forceinline__ void mma_tf32(float d[4], const float4& a, float b0, float b1) {
    asm volatile(
        "mma.sync.aligned.m16n8k8.row.col.f32.tf32.tf32.f32 "
        "{%0,%1,%2,%3},{%4,%5,%6,%7},{%8,%9},{%0,%1,%2,%3};"
        : "+f"(d[0]), "+f"(d[1]), "+f"(d[2]), "+f"(d[3])
        : "r"(__float_as_uint(a.x)), "r"(__float_as_uint(a.y)),
          "r"(__float_as_uint(a.z)), "r"(__float_as_uint(a.w)),
          "r"(__float_as_uint(b0)), "r"(__float_as_uint(b1)));
}

// One k-block (K=8) of D[16,64] += A[16,8] * B[8,64], 3xTF32 split.
// afr: fragment base for (w,kb): [term(2)][lane(32)] float4.
// brow: &B[rowbase][0], interleaved (hi,lo) float2, pitch 68.
__device__ __forceinline__ void gemm_kb(float d[8][4], const float4* __restrict__ afr,
                                        int lane, const float2* __restrict__ brow) {
    const float4 ah = afr[lane];
    const float4 al = afr[32 + lane];
    const int tg = lane & 3, cc = lane >> 2;
    const float2* p0 = brow + tg * 68 + cc;
    const float2* p1 = brow + (tg + 4) * 68 + cc;
#pragma unroll
    for (int nb = 0; nb < 8; ++nb) {
        const float2 v0 = p0[nb * 8];
        const float2 v1 = p1[nb * 8];
        mma_tf32(d[nb], ah, v0.x, v1.x);   // Ah*Bh
        mma_tf32(d[nb], ah, v0.y, v1.y);   // Ah*Bl
        mma_tf32(d[nb], al, v0.x, v1.x);   // Al*Bh
    }
}

// Stage a warp's D strip (rows 16w..16w+15, cols 0..63) into stg[128][68].
__device__ __forceinline__ void stage(const float d[8][4], float* __restrict__ stg,
                                      int w, int lane) {
    const int g = lane >> 2, tg = lane & 3;
    float* p0 = stg + (16 * w + g) * 68 + tg * 2;
    float* p1 = p0 + 8 * 68;
#pragma unroll
    for (int nb = 0; nb < 8; ++nb) {
        *(float2*)(p0 + nb * 8) = make_float2(d[nb][0], d[nb][1]);
        *(float2*)(p1 + nb * 8) = make_float2(d[nb][2], d[nb][3]);
    }
}

extern __shared__ char smem[];

__global__ void __launch_bounds__(NTH, 1)
lstm_model_kernel(const float* __restrict__ x,
                  const float* __restrict__ ln_g, const float* __restrict__ ln_b,
                  const float* __restrict__ Wih0, const float* __restrict__ Whh0,
                  const float* __restrict__ bih0, const float* __restrict__ bhh0,
                  const float* __restrict__ Wih1, const float* __restrict__ Whh1,
                  const float* __restrict__ bih1, const float* __restrict__ bhh1,
                  const float* __restrict__ W1, const float* __restrict__ b1,
                  const float* __restrict__ W2, const float* __restrict__ b2,
                  float* __restrict__ out)
{
    const int tid  = threadIdx.x;
    const int lane = tid & 31;          // also hidden-unit index k
    const int w    = tid >> 5;          // warp 0..7
    const int wb   = 8 * w;             // warp's batch base
    const int bc0  = blockIdx.x * BC;

    float4* AF  = (float4*)(smem + OFF_AF);
    float2* B1X = (float2*)(smem + OFF_B1X);   // [buf][40][68]
    float2* B2  = (float2*)(smem + OFF_B2);    // [buf][32][68]
    float*  stg = (float*)(smem + OFF_STG);
    float*  msc = (float*)(smem + OFF_MISC);

    // ---- zero activation buffers (h1=h2=0 at t=-1) ----
    for (int i = tid; i < (B1X_BYTES + B2_BYTES) / 8; i += NTH)
        ((u64*)(smem + OFF_B1X))[i] = 0;

    // ---- stage A fragments: tf32 hi/lo, mma m16n8k8 row-major layout ----
    // kb 0-3: Whh0 | kb 4: Wih0 | kb 5-8: Whh1 | kb 9-12: Wih1
    for (int idx = tid; idx < 8 * 13 * 2 * 32; idx += NTH) {
        const int ln = idx & 31;
        const int term = (idx >> 5) & 1;
        const int kb = (idx >> 6) % 13;
        const int ws = idx / (13 * 64);
        const int R = 16 * ws, g = ln >> 2, tg = ln & 3;
        const float* Wp; int ldw, C;
        if (kb < 4)      { Wp = Whh0; ldw = 32; C = kb * 8; }
        else if (kb == 4){ Wp = Wih0; ldw = 8;  C = 0; }
        else if (kb < 9) { Wp = Whh1; ldw = 32; C = (kb - 5) * 8; }
        else             { Wp = Wih1; ldw = 32; C = (kb - 9) * 8; }
        float h, l; float4 v;
        tf32s(Wp[(R + g) * ldw + C + tg],       h, l); v.x = term ? l : h;
        tf32s(Wp[(R + 8 + g) * ldw + C + tg],   h, l); v.y = term ? l : h;
        tf32s(Wp[(R + g) * ldw + C + tg + 4],   h, l); v.z = term ? l : h;
        tf32s(Wp[(R + 8 + g) * ldw + C + tg+4], h, l); v.w = term ? l : h;
        AF[idx] = v;
    }

    // ---- biases + FC weights ----
    for (int i = tid; i < 128; i += NTH) {
        msc[i]       = bih0[i] + bhh0[i];
        msc[128 + i] = bih1[i] + bhh1[i];
    }
    for (int i = tid; i < 512; i += NTH) msc[256 + i] = W1[i];
    if (tid < 16) { msc[768 + tid] = b1[tid]; msc[784 + tid] = W2[tid]; }
    if (tid == 0) msc[800] = b2[0];

    // ---- LN slice + x(0) into B1X[0] rows 32..39 ----
    const int   lb  = tid >> 2;
    const int   li  = (tid & 3) * 2;
    const float lg0 = ln_g[li], lg1 = ln_g[li + 1];
    const float lb0 = ln_b[li], lb1 = ln_b[li + 1];
    const float* xg = x + (size_t)(bc0 + lb) * TSTEPS * ISZ + li;
    {
        float2 v = *(const float2*)xg;
        float s = v.x + v.y, ss = v.x * v.x + v.y * v.y;
        s += __shfl_xor_sync(~0u, s, 1); ss += __shfl_xor_sync(~0u, ss, 1);
        s += __shfl_xor_sync(~0u, s, 2); ss += __shfl_xor_sync(~0u, ss, 2);
        float mu = s * 0.125f, rs = rsqrtf(ss * 0.125f - mu * mu + 1e-5f);
        float a0 = (v.x - mu) * rs * lg0 + lb0;
        float a1 = (v.y - mu) * rs * lg1 + lb1;
        float h, l;
        tf32s(a0, h, l); B1X[(32 + li) * 68 + lb]     = make_float2(h, l);
        tf32s(a1, h, l); B1X[(32 + li + 1) * 68 + lb] = make_float2(h, l);
    }
    __syncthreads();

    u64 c1s[4] = {0,0,0,0}, c2s[4] = {0,0,0,0}, h2v[4] = {0,0,0,0};
    const float4* AFW = AF + (w * 13) * 64;

    for (int t = 0; t < TSTEPS; ++t) {
        const int cur = t & 1, nxt = cur ^ 1;

        // ---- phase 1: D_A = wh0*h1 + wx0*x ; D_B = wh1*h2 (tensor pipe) ----
        float dA[8][4], dB[8][4];
#pragma unroll
        for (int nb = 0; nb < 8; ++nb)
#pragma unroll
            for (int e = 0; e < 4; ++e) { dA[nb][e] = 0.0f; dB[nb][e] = 0.0f; }

        const float2* bx = B1X + cur * 40 * 68;
#pragma unroll
        for (int kb = 0; kb < 5; ++kb)
            gemm_kb(dA, AFW + kb * 64, lane, bx + kb * 8 * 68);
        const float2* b2c = B2 + cur * 32 * 68;
#pragma unroll
        for (int kb = 0; kb < 4; ++kb)
            gemm_kb(dB, AFW + (5 + kb) * 64, lane, b2c + kb * 8 * 68);

        // prefetch raw x(t+1)
        float2 xn = make_float2(0.f, 0.f);
        if (t + 1 < TSTEPS) xn = *(const float2*)(xg + (size_t)(t + 1) * ISZ);

        stage(dA, stg, w, lane);
        __syncthreads();

        // ---- act0: gather gates of unit `lane`, update c1, write h1 -> B1X[nxt] ----
        {
            u64 acc[4][4];
#pragma unroll
            for (int gg = 0; gg < 4; ++gg) {
                u64 bb = dup2(msc[gg * 32 + lane]);
                const float* row = stg + (gg * 32 + lane) * 68 + wb;
#pragma unroll
                for (int p = 0; p < 4; ++p) acc[gg][p] = fadd2(bb, *(const u64*)(row + 2 * p));
            }
            float2* hrow = B1X + nxt * 40 * 68 + lane * 68;
#pragma unroll
            for (int p = 0; p < 4; ++p) {
                u64 hv = lstm_act(acc[0][p], acc[1][p], acc[2][p], acc[3][p], c1s[p]);
                float h0, h1; up2(hv, h0, h1);
                float a, b;
                tf32s(h0, a, b); hrow[wb + 2 * p]     = make_float2(a, b);
                tf32s(h1, a, b); hrow[wb + 2 * p + 1] = make_float2(a, b);
            }
        }
        // LN x(t+1) -> B1X[nxt] rows 32..39
        if (t + 1 < TSTEPS) {
            float s = xn.x + xn.y, ss = xn.x * xn.x + xn.y * xn.y;
            s += __shfl_xor_sync(~0u, s, 1); ss += __shfl_xor_sync(~0u, ss, 1);
            s += __shfl_xor_sync(~0u, s, 2); ss += __shfl_xor_sync(~0u, ss, 2);
            float mu = s * 0.125f, rs = rsqrtf(ss * 0.125f - mu * mu + 1e-5f);
            float a0 = (xn.x - mu) * rs * lg0 + lb0;
            float a1 = (xn.y - mu) * rs * lg1 + lb1;
            float h, l;
            tf32s(a0, h, l); B1X[(nxt * 40 + 32 + li) * 68 + lb]     = make_float2(h, l);
            tf32s(a1, h, l); B1X[(nxt * 40 + 32 + li + 1) * 68 + lb] = make_float2(h, l);
        }
        __syncthreads();

        // ---- phase 2: D_B += wx1 * h1(t) ----
        const float2* bxn = B1X + nxt * 40 * 68;
#pragma unroll
        for (int kb = 0; kb < 4; ++kb)
            gemm_kb(dB, AFW + (9 + kb) * 64, lane, bxn + kb * 8 * 68);

        stage(dB, stg, w, lane);
        __syncthreads();

        // ---- act1: update c2, write h2 -> B2[nxt] ----
        {
            u64 acc[4][4];
#pragma unroll
            for (int gg = 0; gg < 4; ++gg) {
                u64 bb = dup2(msc[128 + gg * 32 + lane]);
                const float* row = stg + (gg * 32 + lane) * 68 + wb;
#pragma unroll
                for (int p = 0; p < 4; ++p) acc[gg][p] = fadd2(bb, *(const u64*)(row + 2 * p));
            }
            float2* hrow = B2 + nxt * 32 * 68 + lane * 68;
#pragma unroll
            for (int p = 0; p < 4; ++p) {
                u64 hv = lstm_act(acc[0][p], acc[1][p], acc[2][p], acc[3][p], c2s[p]);
                h2v[p] = hv;
                float h0, h1; up2(hv, h0, h1);
                float a, b;
                tf32s(h0, a, b); hrow[wb + 2 * p]     = make_float2(a, b);
                tf32s(h1, a, b); hrow[wb + 2 * p + 1] = make_float2(a, b);
            }
        }
        __syncthreads();
    }

    // ---- FC head: stage final h2 (fp32) then tanh(relu(h2@W1^T+b1)@W2^T+b2) ----
#pragma unroll
    for (int p = 0; p < 4; ++p) {
        float h0, h1; up2(h2v[p], h0, h1);
        stg[lane * 68 + wb + 2 * p]     = h0;
        stg[lane * 68 + wb + 2 * p + 1] = h1;
    }
    __syncthreads();
    if (tid < BC) {
        float acc2 = msc[800];
#pragma unroll
        for (int f = 0; f < 16; ++f) {
            float s = msc[768 + f];
#pragma unroll
            for (int kk = 0; kk < HID; ++kk)
                s += stg[kk * 68 + tid] * msc[256 + f * HID + kk];
            s = fmaxf(s, 0.0f);
            acc2 += s * msc[784 + f];
        }
        out[bc0 + tid] = tanhfx(acc2);
    }
}

extern "C" void kernel_launch(void* const* d_in, const int* in_sizes, int n_in,
                              void* d_out, int out_size) {
    const float* x    = (const float*)d_in[0];
    const float* ln_g = (const float*)d_in[1];
    const float* ln_b = (const float*)d_in[2];
    const float* Wih0 = (const float*)d_in[3];
    const float* Whh0 = (const float*)d_in[4];
    const float* bih0 = (const float*)d_in[5];
    const float* bhh0 = (const float*)d_in[6];
    const float* Wih1 = (const float*)d_in[7];
    const float* Whh1 = (const float*)d_in[8];
    const float* bih1 = (const float*)d_in[9];
    const float* bhh1 = (const float*)d_in[10];
    const float* W1   = (const float*)d_in[11];
    const float* b1   = (const float*)d_in[12];
    const float* W2   = (const float*)d_in[13];
    const float* b2   = (const float*)d_in[14];
    float* out = (float*)d_out;

    const int nb   = in_sizes[0] / (TSTEPS * ISZ);
    const int grid = nb / BC;   // 128 CTAs
    cudaFuncSetAttribute(lstm_model_kernel,
                         cudaFuncAttributeMaxDynamicSharedMemorySize, SMEM_TOTAL);
    lstm_model_kernel<<<grid, NTH, SMEM_TOTAL>>>(
        x, ln_g, ln_b, Wih0, Whh0, bih0, bhh0,
        Wih1, Whh1, bih1, bhh1, W1, b1, W2, b2, out);
}